// round 2
// baseline (speedup 1.0000x reference)
#include <cuda_runtime.h>
#include <cuda_bf16.h>

#define NPTS 100000
#define BATCH 4096
#define KSEL 10
#define NPART 16
#define PART_SZ (NPTS / NPART)          // 6250
#define RAYS_PER_BLOCK 256
#define RAY_BLOCKS (BATCH / RAYS_PER_BLOCK)  // 16
#define TILE 2048

__device__ float4 g_pts[NPTS];
__device__ float  g_cd[NPART * KSEL * BATCH];
__device__ int    g_ci[NPART * KSEL * BATCH];

#define FLT_BIG 3.4028235e38f

// lexicographic (sq, idx): smaller sq wins; tie -> smaller idx (matches jax top_k)
#define BETTER(a, ia, b, ib) ((a) < (b) || ((a) == (b) && (ia) < (ib)))

__global__ void prep_kernel(const float* __restrict__ xyz) {
    int i = blockIdx.x * blockDim.x + threadIdx.x;
    if (i < NPTS) {
        float x = xyz[3 * i + 0];
        float y = xyz[3 * i + 1];
        float z = xyz[3 * i + 2];
        float xn = (x * x + y * y) + z * z;   // matches jnp.sum(xyz*xyz, axis=1)
        g_pts[i] = make_float4(x, y, z, xn);
    }
}

__global__ __launch_bounds__(RAYS_PER_BLOCK)
void pass1_kernel(const float* __restrict__ rays_o, const float* __restrict__ rays_d) {
    __shared__ float4 tile[TILE];

    int ray  = blockIdx.x * RAYS_PER_BLOCK + threadIdx.x;
    int part = blockIdx.y;
    int p0 = part * PART_SZ;
    int p1 = p0 + PART_SZ;

    // ray center c = o + 3*d ; cn = sum(c*c)
    float cx = rays_o[3 * ray + 0] + rays_d[3 * ray + 0] * 3.0f;
    float cy = rays_o[3 * ray + 1] + rays_d[3 * ray + 1] * 3.0f;
    float cz = rays_o[3 * ray + 2] + rays_d[3 * ray + 2] * 3.0f;
    float cn = (cx * cx + cy * cy) + cz * cz;

    float s[KSEL];
    int   id[KSEL];
#pragma unroll
    for (int k = 0; k < KSEL; k++) { s[k] = FLT_BIG; id[k] = 0x7FFFFFFF; }

    for (int t0 = p0; t0 < p1; t0 += TILE) {
        int cnt = min(TILE, p1 - t0);
        __syncthreads();
        for (int i = threadIdx.x; i < cnt; i += RAYS_PER_BLOCK)
            tile[i] = g_pts[t0 + i];
        __syncthreads();

#pragma unroll 4
        for (int i = 0; i < cnt; i++) {
            float4 pt = tile[i];
            float dot = fmaf(cz, pt.z, fmaf(cy, pt.y, cx * pt.x));
            float sq  = fmaf(-2.0f, dot, cn + pt.w);   // (cn+xn) - 2*dot
            int idx = t0 + i;
            if (BETTER(sq, idx, s[KSEL - 1], id[KSEL - 1])) {
                s[KSEL - 1] = sq; id[KSEL - 1] = idx;
#pragma unroll
                for (int j = KSEL - 1; j > 0; --j) {
                    if (BETTER(s[j], id[j], s[j - 1], id[j - 1])) {
                        float ts = s[j]; s[j] = s[j - 1]; s[j - 1] = ts;
                        int   ti = id[j]; id[j] = id[j - 1]; id[j - 1] = ti;
                    }
                }
            }
        }
    }

#pragma unroll
    for (int k = 0; k < KSEL; k++) {
        g_cd[(part * KSEL + k) * BATCH + ray] = s[k];
        g_ci[(part * KSEL + k) * BATCH + ray] = id[k];
    }
}

__global__ __launch_bounds__(RAYS_PER_BLOCK)
void merge_kernel(const float* __restrict__ features_dc,
                  const float* __restrict__ opacity,
                  float* __restrict__ out) {
    int ray = blockIdx.x * RAYS_PER_BLOCK + threadIdx.x;

    float s[KSEL];
    int   id[KSEL];
#pragma unroll
    for (int k = 0; k < KSEL; k++) { s[k] = FLT_BIG; id[k] = 0x7FFFFFFF; }

    for (int p = 0; p < NPART; p++) {
#pragma unroll
        for (int k = 0; k < KSEL; k++) {
            float sq = g_cd[(p * KSEL + k) * BATCH + ray];
            int  idx = g_ci[(p * KSEL + k) * BATCH + ray];
            if (BETTER(sq, idx, s[KSEL - 1], id[KSEL - 1])) {
                s[KSEL - 1] = sq; id[KSEL - 1] = idx;
#pragma unroll
                for (int j = KSEL - 1; j > 0; --j) {
                    if (BETTER(s[j], id[j], s[j - 1], id[j - 1])) {
                        float ts = s[j]; s[j] = s[j - 1]; s[j - 1] = ts;
                        int   ti = id[j]; id[j] = id[j - 1]; id[j - 1] = ti;
                    }
                }
            }
            // partition lists are sorted lexicographically: once one fails, rest fail
        }
    }

    float wsum = 0.0f, r0 = 0.0f, r1 = 0.0f, r2 = 0.0f;
#pragma unroll
    for (int k = 0; k < KSEL; k++) {
        float d = sqrtf(fmaxf(s[k], 0.0f));
        int i = id[k];
        float o  = 1.0f / (1.0f + expf(-opacity[i]));
        float w  = expf(-d * 0.1f) * o;
        float c0 = 1.0f / (1.0f + expf(-features_dc[3 * i + 0]));
        float c1 = 1.0f / (1.0f + expf(-features_dc[3 * i + 1]));
        float c2 = 1.0f / (1.0f + expf(-features_dc[3 * i + 2]));
        wsum += w;
        r0 = fmaf(w, c0, r0);
        r1 = fmaf(w, c1, r1);
        r2 = fmaf(w, c2, r2);
    }
    float inv = 1.0f / (wsum + 1e-8f);
    out[3 * ray + 0] = r0 * inv;
    out[3 * ray + 1] = r1 * inv;
    out[3 * ray + 2] = r2 * inv;
}

extern "C" void kernel_launch(void* const* d_in, const int* in_sizes, int n_in,
                              void* d_out, int out_size) {
    const float* rays_o      = (const float*)d_in[0];
    const float* rays_d      = (const float*)d_in[1];
    const float* xyz         = (const float*)d_in[2];
    const float* features_dc = (const float*)d_in[3];
    const float* opacity     = (const float*)d_in[4];
    float* out = (float*)d_out;

    prep_kernel<<<(NPTS + 255) / 256, 256>>>(xyz);
    pass1_kernel<<<dim3(RAY_BLOCKS, NPART), RAYS_PER_BLOCK>>>(rays_o, rays_d);
    merge_kernel<<<RAY_BLOCKS, RAYS_PER_BLOCK>>>(features_dc, opacity, out);
}

// round 3
// speedup vs baseline: 1.1571x; 1.1571x over previous
#include <cuda_runtime.h>
#include <cuda_bf16.h>

#define NPTS 100000
#define BATCH 4096
#define KSEL 10
#define SAMPLE_N 4096
#define SPART 32
#define SPART_SZ (SAMPLE_N / SPART)     // 128
#define NPART 37
#define PART_SZ 2703                     // ceil(100000/37); 37*2703 = 100011
#define RPB 256
#define RAY_BLOCKS (BATCH / RPB)         // 16
#define BUFCAP 2048
#define FLT_BIG 3.4028235e38f

__device__ float4 g_pts[NPTS];
__device__ float  g_samp[SPART * KSEL * BATCH];
__device__ float  g_thr[BATCH];
__device__ int    g_cnt[BATCH];
__device__ int    g_cand[BUFCAP * BATCH];   // slot-major: [slot*BATCH + ray]

// lexicographic (sq, idx): smaller sq wins; tie -> smaller idx (matches jax top_k)
#define BETTER(a, ia, b, ib) ((a) < (b) || ((a) == (b) && (ia) < (ib)))

// exact reference-form squared distance (identical expression everywhere)
#define SQDIST(pt) fmaf(-2.0f, fmaf(cz, (pt).z, fmaf(cy, (pt).y, cx * (pt).x)), cn + (pt).w)

#define LOAD_CENTER(ray)                                            \
    float cx = rays_o[3 * (ray) + 0] + rays_d[3 * (ray) + 0] * 3.0f; \
    float cy = rays_o[3 * (ray) + 1] + rays_d[3 * (ray) + 1] * 3.0f; \
    float cz = rays_o[3 * (ray) + 2] + rays_d[3 * (ray) + 2] * 3.0f; \
    float cn = (cx * cx + cy * cy) + cz * cz;

__global__ void prep_kernel(const float* __restrict__ xyz) {
    int i = blockIdx.x * blockDim.x + threadIdx.x;
    if (i < NPTS) {
        float x = xyz[3 * i + 0];
        float y = xyz[3 * i + 1];
        float z = xyz[3 * i + 2];
        float xn = (x * x + y * y) + z * z;
        g_pts[i] = make_float4(x, y, z, xn);
    }
}

// A1: per-ray top-10 (sq only) over one 128-point sample partition
__global__ __launch_bounds__(RPB)
void sample_topk_kernel(const float* __restrict__ rays_o, const float* __restrict__ rays_d) {
    __shared__ float4 tile[SPART_SZ];
    int ray  = blockIdx.x * RPB + threadIdx.x;
    int part = blockIdx.y;

    if (threadIdx.x < SPART_SZ)
        tile[threadIdx.x] = g_pts[part * SPART_SZ + threadIdx.x];

    LOAD_CENTER(ray);

    float s[KSEL];
#pragma unroll
    for (int k = 0; k < KSEL; k++) s[k] = FLT_BIG;

    __syncthreads();
#pragma unroll 4
    for (int i = 0; i < SPART_SZ; i++) {
        float sq = SQDIST(tile[i]);
        if (sq < s[KSEL - 1]) {
            s[KSEL - 1] = sq;
#pragma unroll
            for (int j = KSEL - 1; j > 0; --j)
                if (s[j] < s[j - 1]) { float t = s[j]; s[j] = s[j - 1]; s[j - 1] = t; }
        }
    }
#pragma unroll
    for (int k = 0; k < KSEL; k++)
        g_samp[(part * KSEL + k) * BATCH + ray] = s[k];
}

// A2: per-ray merge of 32x10 sample sqs -> threshold; zero candidate counter
__global__ __launch_bounds__(RPB)
void threshold_kernel() {
    int ray = blockIdx.x * RPB + threadIdx.x;
    float s[KSEL];
#pragma unroll
    for (int k = 0; k < KSEL; k++) s[k] = FLT_BIG;

    for (int p = 0; p < SPART; p++) {
#pragma unroll
        for (int k = 0; k < KSEL; k++) {
            float v = g_samp[(p * KSEL + k) * BATCH + ray];
            if (v < s[KSEL - 1]) {
                s[KSEL - 1] = v;
#pragma unroll
                for (int j = KSEL - 1; j > 0; --j)
                    if (s[j] < s[j - 1]) { float t = s[j]; s[j] = s[j - 1]; s[j - 1] = t; }
            }
        }
    }
    g_thr[ray] = s[KSEL - 1];
    g_cnt[ray] = 0;
}

// B: full branch-light scan; emit candidate indices below threshold
__global__ __launch_bounds__(RPB)
void scan_kernel(const float* __restrict__ rays_o, const float* __restrict__ rays_d) {
    __shared__ float4 tile[PART_SZ];
    int ray  = blockIdx.x * RPB + threadIdx.x;
    int part = blockIdx.y;
    int p0   = part * PART_SZ;
    int cntp = min(PART_SZ, NPTS - p0);

    for (int i = threadIdx.x; i < cntp; i += RPB)
        tile[i] = g_pts[p0 + i];

    LOAD_CENTER(ray);
    // inflation covers any cross-kernel FP-contraction difference (rel err <= ~1.2e-7 * (cn+1))
    float tt = g_thr[ray] + 1e-5f * (cn + 1.0f);

    __syncthreads();
#pragma unroll 8
    for (int i = 0; i < cntp; i++) {
        float sq = SQDIST(tile[i]);
        if (sq <= tt) {
            int slot = atomicAdd(&g_cnt[ray], 1);
            if (slot < BUFCAP) g_cand[slot * BATCH + ray] = p0 + i;
        }
    }
}

// C: exact top-10 among candidates (order-independent -> deterministic) + epilogue
__global__ __launch_bounds__(RPB)
void final_kernel(const float* __restrict__ rays_o, const float* __restrict__ rays_d,
                  const float* __restrict__ features_dc, const float* __restrict__ opacity,
                  float* __restrict__ out) {
    int ray = blockIdx.x * RPB + threadIdx.x;
    LOAD_CENTER(ray);

    int n = min(g_cnt[ray], BUFCAP);

    float s[KSEL];
    int   id[KSEL];
#pragma unroll
    for (int k = 0; k < KSEL; k++) { s[k] = FLT_BIG; id[k] = 0x7FFFFFFF; }

    for (int j = 0; j < n; j++) {
        int idx = g_cand[j * BATCH + ray];
        float4 pt = g_pts[idx];
        float sq = SQDIST(pt);
        if (BETTER(sq, idx, s[KSEL - 1], id[KSEL - 1])) {
            s[KSEL - 1] = sq; id[KSEL - 1] = idx;
#pragma unroll
            for (int jj = KSEL - 1; jj > 0; --jj) {
                if (BETTER(s[jj], id[jj], s[jj - 1], id[jj - 1])) {
                    float ts = s[jj]; s[jj] = s[jj - 1]; s[jj - 1] = ts;
                    int   ti = id[jj]; id[jj] = id[jj - 1]; id[jj - 1] = ti;
                }
            }
        }
    }

    float wsum = 0.0f, r0 = 0.0f, r1 = 0.0f, r2 = 0.0f;
#pragma unroll
    for (int k = 0; k < KSEL; k++) {
        float d = sqrtf(fmaxf(s[k], 0.0f));
        int i = min(id[k], NPTS - 1);            // safety clamp (n >= 10 by construction)
        float o  = 1.0f / (1.0f + expf(-opacity[i]));
        float w  = expf(-d * 0.1f) * o;
        if (s[k] >= FLT_BIG) w = 0.0f;
        float c0 = 1.0f / (1.0f + expf(-features_dc[3 * i + 0]));
        float c1 = 1.0f / (1.0f + expf(-features_dc[3 * i + 1]));
        float c2 = 1.0f / (1.0f + expf(-features_dc[3 * i + 2]));
        wsum += w;
        r0 = fmaf(w, c0, r0);
        r1 = fmaf(w, c1, r1);
        r2 = fmaf(w, c2, r2);
    }
    float inv = 1.0f / (wsum + 1e-8f);
    out[3 * ray + 0] = r0 * inv;
    out[3 * ray + 1] = r1 * inv;
    out[3 * ray + 2] = r2 * inv;
}

extern "C" void kernel_launch(void* const* d_in, const int* in_sizes, int n_in,
                              void* d_out, int out_size) {
    const float* rays_o      = (const float*)d_in[0];
    const float* rays_d      = (const float*)d_in[1];
    const float* xyz         = (const float*)d_in[2];
    const float* features_dc = (const float*)d_in[3];
    const float* opacity     = (const float*)d_in[4];
    float* out = (float*)d_out;

    prep_kernel<<<(NPTS + 255) / 256, 256>>>(xyz);
    sample_topk_kernel<<<dim3(RAY_BLOCKS, SPART), RPB>>>(rays_o, rays_d);
    threshold_kernel<<<RAY_BLOCKS, RPB>>>();
    scan_kernel<<<dim3(RAY_BLOCKS, NPART), RPB>>>(rays_o, rays_d);
    final_kernel<<<RAY_BLOCKS, RPB>>>(rays_o, rays_d, features_dc, opacity, out);
}